// round 2
// baseline (speedup 1.0000x reference)
#include <cuda_runtime.h>

// SMPL forward kinematics, HBM-bound streaming kernel. Round 2:
// 8 independent single-warp blocks per SM instead of 2x4-warp blocks, so the
// load phases of different blocks tile over each other's compute/store phases
// and keep DRAM busy.
//
// Math (G-conjugations cancel):
//   out[b,j] = out[b,P[j]] + R_{b,P[j]} * v_j,  out[b,0] = 0
//   v_j = (off[j][1], off[j][2], off[j][0])
//
// Per block (32 threads = 32 batches):
//  1) coalesced LDG.128 of 32*54 float4 -> smem transposed [elem][batch]
//  2) per-thread FK from smem (lane-consecutive LDS.128, conflict-free)
//  3) results transposed back through smem -> coalesced STG.128

#define NB   32           // batches per block (== blockDim.x)
#define NF4  54           // float4 per batch, input  (24*9 floats)
#define OF4  18           // float4 per batch, output (24*3 floats)
#define SMEM_BYTES (NF4 * NB * 16)   // 27,648 B -> 8 blocks/SM

__global__ __launch_bounds__(NB, 8)
void smpl_fk_kernel(const float4* __restrict__ orient,
                    const float*  __restrict__ off,
                    float4*       __restrict__ out,
                    int Btotal)
{
    __shared__ float4 sm[NF4 * NB];
    const int tid = threadIdx.x;
    const int b0  = blockIdx.x * NB;
    const int nb  = (Btotal - b0 < NB) ? (Btotal - b0) : NB;   // tail guard

    // ---------------- stage in: coalesced global -> transposed smem ----------------
    {
        const long long gbase = (long long)b0 * NF4;
        const int total = nb * NF4;
#pragma unroll
        for (int it = 0; it < NF4; ++it) {
            const int g = it * NB + tid;
            if (g < total) {
                const int b = g / NF4;
                const int e = g - b * NF4;
                sm[e * NB + b] = orient[gbase + g];
            }
        }
    }
    __syncthreads();

    // ---------------- compute: per-thread FK ----------------
    float px[24], py[24], pz[24];

    if (tid < nb) {
        constexpr int PAR[24] = {-1,0,1,2,3,0,5,6,7,0,9,10,11,12,11,14,15,16,17,11,19,20,21,22};
        px[0] = 0.f; py[0] = 0.f; pz[0] = 0.f;
#pragma unroll
        for (int j = 1; j < 24; ++j) {
            const int p  = PAR[j];
            const int w0 = 9 * p;          // first word of matrix p within the batch record
            const int c0 = w0 >> 2;        // first float4 chunk (compile-time)
            const int r  = w0 & 3;         // word offset inside chunk (compile-time)

            const float4 A = sm[(c0 + 0) * NB + tid];
            const float4 Bq= sm[(c0 + 1) * NB + tid];
            const float4 C = sm[(c0 + 2) * NB + tid];
            float m[12];
            m[0]=A.x;  m[1]=A.y;  m[2]=A.z;  m[3]=A.w;
            m[4]=Bq.x; m[5]=Bq.y; m[6]=Bq.z; m[7]=Bq.w;
            m[8]=C.x;  m[9]=C.y;  m[10]=C.z; m[11]=C.w;

            // v_j = G * off_j  (permutation)
            const float vx = __ldg(off + j * 3 + 1);
            const float vy = __ldg(off + j * 3 + 2);
            const float vz = __ldg(off + j * 3 + 0);

            px[j] = fmaf(m[r+0], vx, fmaf(m[r+1], vy, fmaf(m[r+2], vz, px[p])));
            py[j] = fmaf(m[r+3], vx, fmaf(m[r+4], vy, fmaf(m[r+5], vz, py[p])));
            pz[j] = fmaf(m[r+6], vx, fmaf(m[r+7], vy, fmaf(m[r+8], vz, pz[p])));
        }
    }
    __syncthreads();   // smem about to be reused (cheap: single-warp block)

    // ---------------- stage out: registers -> transposed smem ----------------
    if (tid < nb) {
#pragma unroll
        for (int e = 0; e < OF4; ++e) {
            float4 o;
            // word w = 4*e + c maps to joint w/3, component w%3 (all compile-time)
            #define COMPW(w) (((w) % 3 == 0) ? px[(w) / 3] : (((w) % 3 == 1) ? py[(w) / 3] : pz[(w) / 3]))
            o.x = COMPW(4 * e + 0);
            o.y = COMPW(4 * e + 1);
            o.z = COMPW(4 * e + 2);
            o.w = COMPW(4 * e + 3);
            #undef COMPW
            sm[e * NB + tid] = o;
        }
    }
    __syncthreads();

    // ---------------- write out: transposed smem -> coalesced global ----------------
    {
        const long long obase = (long long)b0 * OF4;
        const int total = nb * OF4;
#pragma unroll
        for (int it = 0; it < OF4; ++it) {
            const int g = it * NB + tid;
            if (g < total) {
                const int b = g / OF4;
                const int e = g - b * OF4;
                out[obase + g] = sm[e * NB + b];
            }
        }
    }
}

extern "C" void kernel_launch(void* const* d_in, const int* in_sizes, int n_in,
                              void* d_out, int out_size)
{
    const float4* orient = (const float4*)d_in[0];   // (B, 24, 3, 3) fp32
    const float*  off    = (const float* )d_in[1];   // (24, 3) fp32
    float4*       out    = (float4*)d_out;           // (B, 24, 3) fp32

    const int B = in_sizes[0] / 216;
    const int grid = (B + NB - 1) / NB;

    smpl_fk_kernel<<<grid, NB>>>(orient, off, out, B);
}

// round 3
// speedup vs baseline: 1.2937x; 1.2937x over previous
#include <cuda_runtime.h>

// SMPL forward kinematics, HBM-bound streaming kernel. Round 3:
// 8 independent single-warp blocks per SM (round-2 structure) + XOR-swizzled
// shared memory so BOTH the transpose phases and the compute phase are
// bank-conflict-free with zero padding (keeps smem at 27,648 B -> 8 blocks/SM).
//
// Math (G-conjugations cancel):
//   out[b,j] = out[b,P[j]] + R_{b,P[j]} * v_j,  out[b,0] = 0
//   v_j = (off[j][1], off[j][2], off[j][0])
//
// Per block (32 threads = 32 batches):
//  1) coalesced LDG.128 of 32*54 float4 -> smem transposed [elem][batch], swizzled
//  2) per-thread FK from smem (swizzle is a lane permutation -> conflict-free)
//  3) results transposed back through smem -> coalesced STG.128

#define NB   32           // batches per block (== blockDim.x)
#define NF4  54           // float4 per batch, input  (24*9 floats)
#define OF4  18           // float4 per batch, output (24*3 floats)

// swizzled smem index for logical [e][b]; conflict-free in both access patterns
#define SWZ(e, b) ((e) * NB + (((b) ^ (e)) & (NB - 1)) )

__global__ __launch_bounds__(NB, 8)
void smpl_fk_kernel(const float4* __restrict__ orient,
                    const float*  __restrict__ off,
                    float4*       __restrict__ out,
                    int Btotal)
{
    __shared__ float4 sm[NF4 * NB];   // 27,648 B
    const int tid = threadIdx.x;
    const int b0  = blockIdx.x * NB;
    const int nb  = (Btotal - b0 < NB) ? (Btotal - b0) : NB;   // tail guard

    // ---------------- stage in: coalesced global -> transposed smem ----------------
    {
        const long long gbase = (long long)b0 * NF4;
        const int total = nb * NF4;
#pragma unroll
        for (int it = 0; it < NF4; ++it) {
            const int g = it * NB + tid;
            if (g < total) {
                const int b = g / NF4;
                const int e = g - b * NF4;
                sm[SWZ(e, b)] = orient[gbase + g];
            }
        }
    }
    __syncthreads();

    // ---------------- compute: per-thread FK ----------------
    float px[24], py[24], pz[24];

    if (tid < nb) {
        constexpr int PAR[24] = {-1,0,1,2,3,0,5,6,7,0,9,10,11,12,11,14,15,16,17,11,19,20,21,22};
        px[0] = 0.f; py[0] = 0.f; pz[0] = 0.f;
#pragma unroll
        for (int j = 1; j < 24; ++j) {
            const int p  = PAR[j];
            const int w0 = 9 * p;          // first word of matrix p within the batch record
            const int c0 = w0 >> 2;        // first float4 chunk (compile-time)
            const int r  = w0 & 3;         // word offset inside chunk (compile-time)

            const float4 A = sm[SWZ(c0 + 0, tid)];
            const float4 Bq= sm[SWZ(c0 + 1, tid)];
            const float4 C = sm[SWZ(c0 + 2, tid)];
            float m[12];
            m[0]=A.x;  m[1]=A.y;  m[2]=A.z;  m[3]=A.w;
            m[4]=Bq.x; m[5]=Bq.y; m[6]=Bq.z; m[7]=Bq.w;
            m[8]=C.x;  m[9]=C.y;  m[10]=C.z; m[11]=C.w;

            // v_j = G * off_j  (permutation)
            const float vx = __ldg(off + j * 3 + 1);
            const float vy = __ldg(off + j * 3 + 2);
            const float vz = __ldg(off + j * 3 + 0);

            px[j] = fmaf(m[r+0], vx, fmaf(m[r+1], vy, fmaf(m[r+2], vz, px[p])));
            py[j] = fmaf(m[r+3], vx, fmaf(m[r+4], vy, fmaf(m[r+5], vz, py[p])));
            pz[j] = fmaf(m[r+6], vx, fmaf(m[r+7], vy, fmaf(m[r+8], vz, pz[p])));
        }
    }
    __syncthreads();   // smem about to be reused (cheap: single-warp block)

    // ---------------- stage out: registers -> transposed smem ----------------
    if (tid < nb) {
#pragma unroll
        for (int e = 0; e < OF4; ++e) {
            float4 o;
            // word w = 4*e + c maps to joint w/3, component w%3 (all compile-time)
            #define COMPW(w) (((w) % 3 == 0) ? px[(w) / 3] : (((w) % 3 == 1) ? py[(w) / 3] : pz[(w) / 3]))
            o.x = COMPW(4 * e + 0);
            o.y = COMPW(4 * e + 1);
            o.z = COMPW(4 * e + 2);
            o.w = COMPW(4 * e + 3);
            #undef COMPW
            sm[SWZ(e, tid)] = o;
        }
    }
    __syncthreads();

    // ---------------- write out: transposed smem -> coalesced global ----------------
    {
        const long long obase = (long long)b0 * OF4;
        const int total = nb * OF4;
#pragma unroll
        for (int it = 0; it < OF4; ++it) {
            const int g = it * NB + tid;
            if (g < total) {
                const int b = g / OF4;
                const int e = g - b * OF4;
                out[obase + g] = sm[SWZ(e, b)];
            }
        }
    }
}

extern "C" void kernel_launch(void* const* d_in, const int* in_sizes, int n_in,
                              void* d_out, int out_size)
{
    const float4* orient = (const float4*)d_in[0];   // (B, 24, 3, 3) fp32
    const float*  off    = (const float* )d_in[1];   // (24, 3) fp32
    float4*       out    = (float4*)d_out;           // (B, 24, 3) fp32

    const int B = in_sizes[0] / 216;
    const int grid = (B + NB - 1) / NB;

    smpl_fk_kernel<<<grid, NB>>>(orient, off, out, B);
}